// round 1
// baseline (speedup 1.0000x reference)
#include <cuda_runtime.h>
#include <cstdint>
#include <cmath>

// Problem constants
#define B_   4
#define T_   4096
#define D_   768
#define N_   256
#define HID_ 200
#define P_   32640          // N*(N-1)/2

// Stage-2 tiling
#define TM      64          // pairs per block
#define KC1     32          // K chunk layer 1
#define KC2     40          // K chunk layer 2 (200 = 5*40)
#define WPAD    208         // padded HID (8 col-groups * 26)
#define PRODPAD 33          // 64 x 33 (odd pad -> conflict-free)
#define H1PAD   201         // 64 x 201 (odd pad -> conflict-free)
#define NCOL    26          // columns per thread-col-group (13 f32x2 packs)

typedef unsigned long long ull;

// Scratch (device globals; no cudaMalloc allowed)
__device__ float g_emb[B_ * N_ * D_];          // gathered embeddings
__device__ float g_AB[B_ * N_ * 2 * HID_];     // A (i-term + b1) | B (j-term)
__device__ float g_S[B_ * N_ * N_];            // pair scores (strict lower tri)

// ---------------- f32x2 helpers ----------------
__device__ __forceinline__ ull pack2(float x, float y) {
    ull r;
    asm("mov.b64 %0, {%1, %2};" : "=l"(r) : "r"(__float_as_uint(x)), "r"(__float_as_uint(y)));
    return r;
}
__device__ __forceinline__ ull bcast2(float x) {
    ull r;
    asm("mov.b64 %0, {%1, %1};" : "=l"(r) : "r"(__float_as_uint(x)));
    return r;
}
__device__ __forceinline__ float lo32(ull v) { return __uint_as_float((unsigned)v); }
__device__ __forceinline__ float hi32(ull v) { return __uint_as_float((unsigned)(v >> 32)); }
__device__ __forceinline__ void fma2(ull& acc, ull a, ull w) {
    asm("fma.rn.f32x2 %0, %1, %2, %0;" : "+l"(acc) : "l"(a), "l"(w));
}

// ---------------- Stage 1: gather + per-node W1a/W1b precompute ----------------
// block = (b, n). Writes g_emb row and g_AB row (A part folds in b1).
__global__ void __launch_bounds__(256) stage1_kernel(
    const float* __restrict__ event_embed, const int* __restrict__ event_idx,
    const float* __restrict__ W1, const float* __restrict__ b1)
{
    __shared__ float e[D_];
    int blk = blockIdx.x;              // 0..B_*N_-1
    int b = blk >> 8, n = blk & 255;
    int t = event_idx[b * N_ + n];
    const float* src = event_embed + ((size_t)b * T_ + t) * D_;
    float* dst = g_emb + (size_t)(b * N_ + n) * D_;
    for (int d = threadIdx.x; d < D_; d += 256) {
        float v = src[d];
        e[d] = v;
        dst[d] = v;
    }
    __syncthreads();
    for (int h = threadIdx.x; h < 2 * HID_; h += 256) {
        const float* w;
        int col;
        float acc;
        if (h < HID_) { col = h;        w = W1;               acc = b1[h]; }
        else          { col = h - HID_; w = W1 + (size_t)D_ * HID_; acc = 0.f; }
        #pragma unroll 8
        for (int d = 0; d < D_; ++d)
            acc = fmaf(e[d], w[(size_t)d * HID_ + col], acc);
        g_AB[(size_t)(b * N_ + n) * (2 * HID_) + h] = acc;
    }
}

// ---------------- Stage 2: fused pair MLP ----------------
// grid (P_/TM, B_), 256 threads. Thread (tr = tid&31, tc = tid>>5).
// Thread owns pair-rows {tr, tr+32} and cols [tc*26, tc*26+25] (13 f32x2 packs).
__global__ void __launch_bounds__(256, 2) stage2_kernel(
    const float* __restrict__ W1, const float* __restrict__ W2,
    const float* __restrict__ b2, const float* __restrict__ W3,
    const float* __restrict__ b3)
{
    extern __shared__ float sm[];
    float* prod = sm;                               // [TM][PRODPAD]
    float* ws   = prod + TM * PRODPAD;              // [KC2][WPAD]
    float* h1s  = ws + KC2 * WPAD;                  // [TM][H1PAD]
    int*   iis  = (int*)(h1s + TM * H1PAD);         // [TM]
    int*   jjs  = iis + TM;                         // [TM]
    float* w3s  = (float*)(jjs + TM);               // [WPAD]

    const int tid = threadIdx.x;
    const int tr  = tid & 31;
    const int tc  = tid >> 5;
    const int b   = blockIdx.y;
    const int p0  = blockIdx.x * TM;

    // pair (i, j) from linear index of strict-lower-tri, row-major
    if (tid < TM) {
        int p = p0 + tid;
        int i = (int)((1.0 + sqrt(1.0 + 8.0 * (double)p)) * 0.5);
        while (i * (i - 1) / 2 > p) --i;
        while ((i + 1) * i / 2 <= p) ++i;
        iis[tid] = i;
        jjs[tid] = p - i * (i - 1) / 2;
    }
    for (int h = tid; h < WPAD; h += 256)
        w3s[h] = (h < HID_) ? W3[h] : 0.f;
    __syncthreads();

    const int row0 = tr, row1 = tr + 32;
    const int i0 = iis[row0], j0 = jjs[row0];
    const int i1 = iis[row1], j1 = jjs[row1];

    ull acc0[13], acc1[13];
    // init layer-1 accumulators with A_i + B_j (b1 already folded into A)
    {
        const float* Ai0 = g_AB + (size_t)(b * N_ + i0) * (2 * HID_);
        const float* Bj0 = g_AB + (size_t)(b * N_ + j0) * (2 * HID_) + HID_;
        const float* Ai1 = g_AB + (size_t)(b * N_ + i1) * (2 * HID_);
        const float* Bj1 = g_AB + (size_t)(b * N_ + j1) * (2 * HID_) + HID_;
        #pragma unroll
        for (int c = 0; c < 13; ++c) {
            int col = tc * NCOL + 2 * c;
            float x0 = 0.f, y0 = 0.f, x1 = 0.f, y1 = 0.f;
            if (col < HID_) {
                x0 = Ai0[col] + Bj0[col];
                y0 = Ai0[col + 1] + Bj0[col + 1];
                x1 = Ai1[col] + Bj1[col];
                y1 = Ai1[col + 1] + Bj1[col + 1];
            }
            acc0[c] = pack2(x0, y0);
            acc1[c] = pack2(x1, y1);
        }
    }

    const float* embB = g_emb + (size_t)b * N_ * D_;

    // ----- Layer 1: acc += (emb_i * emb_j) @ W1c -----
    for (int k0 = 0; k0 < D_; k0 += KC1) {
        __syncthreads();
        // W1c chunk (rows 2*D_ + k0 .. +KC1), padded cols zeroed
        for (int idx = tid; idx < KC1 * WPAD; idx += 256) {
            int k = idx / WPAD, h = idx - k * WPAD;
            ws[k * WPAD + h] = (h < HID_)
                ? W1[(size_t)(2 * D_ + k0 + k) * HID_ + h] : 0.f;
        }
        // pair products chunk
        for (int idx = tid; idx < TM * KC1; idx += 256) {
            int p = idx >> 5, k = idx & 31;
            int kk = k0 + k;
            float vi = embB[(size_t)iis[p] * D_ + kk];
            float vj = embB[(size_t)jjs[p] * D_ + kk];
            prod[p * PRODPAD + k] = vi * vj;
        }
        __syncthreads();
        #pragma unroll 8
        for (int k = 0; k < KC1; ++k) {
            ull a0p = bcast2(prod[row0 * PRODPAD + k]);
            ull a1p = bcast2(prod[row1 * PRODPAD + k]);
            const ull* wrow = (const ull*)(ws + k * WPAD + tc * NCOL);
            #pragma unroll
            for (int c = 0; c < 13; ++c) {
                ull w = wrow[c];
                fma2(acc0[c], a0p, w);
                fma2(acc1[c], a1p, w);
            }
        }
    }

    // relu -> h1s; re-init accumulators with b2
    #pragma unroll
    for (int c = 0; c < 13; ++c) {
        int col = tc * NCOL + 2 * c;
        if (col < HID_) {
            h1s[row0 * H1PAD + col]     = fmaxf(lo32(acc0[c]), 0.f);
            h1s[row0 * H1PAD + col + 1] = fmaxf(hi32(acc0[c]), 0.f);
            h1s[row1 * H1PAD + col]     = fmaxf(lo32(acc1[c]), 0.f);
            h1s[row1 * H1PAD + col + 1] = fmaxf(hi32(acc1[c]), 0.f);
        }
        float bx = 0.f, by = 0.f;
        if (col < HID_) { bx = b2[col]; by = b2[col + 1]; }
        ull bp = pack2(bx, by);
        acc0[c] = bp;
        acc1[c] = bp;
    }

    // ----- Layer 2: acc += h1 @ W2 -----
    for (int k0 = 0; k0 < HID_; k0 += KC2) {
        __syncthreads();
        for (int idx = tid; idx < KC2 * WPAD; idx += 256) {
            int k = idx / WPAD, h = idx - k * WPAD;
            ws[k * WPAD + h] = (h < HID_)
                ? W2[(size_t)(k0 + k) * HID_ + h] : 0.f;
        }
        __syncthreads();
        const float* h1r0 = h1s + row0 * H1PAD + k0;
        const float* h1r1 = h1s + row1 * H1PAD + k0;
        #pragma unroll 8
        for (int k = 0; k < KC2; ++k) {
            ull a0p = bcast2(h1r0[k]);
            ull a1p = bcast2(h1r1[k]);
            const ull* wrow = (const ull*)(ws + k * WPAD + tc * NCOL);
            #pragma unroll
            for (int c = 0; c < 13; ++c) {
                ull w = wrow[c];
                fma2(acc0[c], a0p, w);
                fma2(acc1[c], a1p, w);
            }
        }
    }

    // ----- Layer 3: s = relu(h2) @ W3 + b3, reduce across col-groups -----
    float s0 = 0.f, s1 = 0.f;
    #pragma unroll
    for (int c = 0; c < 13; ++c) {
        int col = tc * NCOL + 2 * c;
        float w0 = w3s[col], w1v = w3s[col + 1];   // zero in pad region
        s0 = fmaf(fmaxf(lo32(acc0[c]), 0.f), w0, s0);
        s0 = fmaf(fmaxf(hi32(acc0[c]), 0.f), w1v, s0);
        s1 = fmaf(fmaxf(lo32(acc1[c]), 0.f), w0, s1);
        s1 = fmaf(fmaxf(hi32(acc1[c]), 0.f), w1v, s1);
    }
    __syncthreads();
    float* sred = prod;                 // reuse: [TM][8]
    sred[row0 * 8 + tc] = s0;
    sred[row1 * 8 + tc] = s1;
    __syncthreads();
    if (tid < TM) {
        float s = b3[0];
        #pragma unroll
        for (int c = 0; c < 8; ++c) s += sred[tid * 8 + c];
        int i = iis[tid], j = jjs[tid];
        g_S[(size_t)(b * N_ + i) * N_ + j] = s;
    }
}

// ---------------- Stage 3: masked row softmax ----------------
// block per (b, i); logits: s[j] for j<i, 0 at j==i, -inf for j>i.
__global__ void __launch_bounds__(128) softmax_kernel(float* __restrict__ out)
{
    int blk = blockIdx.x;               // b*N_ + i
    int i = blk & 255;
    const float* srow = g_S + (size_t)blk * N_;
    float* orow = out + (size_t)blk * N_;
    __shared__ float redm[4], redz[4];
    int tid = threadIdx.x;

    float m = (tid == 0) ? 0.f : -INFINITY;   // diagonal logit = 0
    for (int j = tid; j < i; j += 128) m = fmaxf(m, srow[j]);
    #pragma unroll
    for (int o = 16; o; o >>= 1) m = fmaxf(m, __shfl_xor_sync(0xffffffffu, m, o));
    if ((tid & 31) == 0) redm[tid >> 5] = m;
    __syncthreads();
    m = fmaxf(fmaxf(redm[0], redm[1]), fmaxf(redm[2], redm[3]));

    float z = (tid == 0) ? expf(-m) : 0.f;    // diagonal term
    for (int j = tid; j < i; j += 128) z += expf(srow[j] - m);
    #pragma unroll
    for (int o = 16; o; o >>= 1) z += __shfl_xor_sync(0xffffffffu, z, o);
    if ((tid & 31) == 0) redz[tid >> 5] = z;
    __syncthreads();
    z = redz[0] + redz[1] + redz[2] + redz[3];
    float invz = 1.f / z;

    for (int j = tid; j < N_; j += 128) {
        float o_;
        if (j < i)       o_ = expf(srow[j] - m) * invz;
        else if (j == i) o_ = expf(-m) * invz;
        else             o_ = -1000.0f;
        orow[j] = o_;
    }
}

// ---------------- launch ----------------
extern "C" void kernel_launch(void* const* d_in, const int* in_sizes, int n_in,
                              void* d_out, int out_size)
{
    (void)in_sizes; (void)n_in; (void)out_size;
    const float* event_embed = (const float*)d_in[0];
    const int*   event_idx   = (const int*)d_in[1];
    const float* W1 = (const float*)d_in[2];
    const float* b1 = (const float*)d_in[3];
    const float* W2 = (const float*)d_in[4];
    const float* b2 = (const float*)d_in[5];
    const float* W3 = (const float*)d_in[6];
    const float* b3 = (const float*)d_in[7];
    float* out = (float*)d_out;

    const size_t smem_bytes =
        (size_t)(TM * PRODPAD + KC2 * WPAD + TM * H1PAD) * sizeof(float)
        + 2 * TM * sizeof(int) + WPAD * sizeof(float);   // = 94528

    cudaFuncSetAttribute(stage2_kernel,
                         cudaFuncAttributeMaxDynamicSharedMemorySize,
                         (int)smem_bytes);

    stage1_kernel<<<B_ * N_, 256>>>(event_embed, event_idx, W1, b1);

    dim3 grid2(P_ / TM, B_);
    stage2_kernel<<<grid2, 256, smem_bytes>>>(W1, W2, b2, W3, b3);

    softmax_kernel<<<B_ * N_, 128>>>(out);
}

// round 3
// speedup vs baseline: 2.7044x; 2.7044x over previous
#include <cuda_runtime.h>
#include <cuda_bf16.h>
#include <cstdint>
#include <cmath>

// ---------------- problem constants ----------------
#define B_   4
#define T_   4096
#define D_   768
#define N_   256
#define HID_ 200
#define P_   32640         // N*(N-1)/2
#define NPAD 208
#define MT   128           // pairs per CTA
#define THREADS 256

// ---------------- SMEM layout (stage 2) ----------------
#define BB_OFF   0
#define BB_SZ    33280     // per buf: Bh[208][40]bf16 (16640) + Bl (16640)
#define AB_OFF   66560
#define AB_SZ    20480     // per buf: Ah[128][40] (10240) + Al (10240)
#define H1H_OFF  66560     // h1 hi [128][216] bf16 (55296), overlaps A bufs (phase-disjoint)
#define H1L_OFF  121856
#define EXT_OFF  177152    // iis(512) jjs(512) b2s(832) w3s(832)
#define SMEM_TOTAL 179840
#define SA 40              // A tile stride (bf16 elems) -> 80B, ldmatrix conflict-free
#define SB 40
#define SH 216             // h1 stride -> 432B, conflict-free

// ---------------- scratch (device globals) ----------------
__device__ __align__(16) float g_emb[B_ * N_ * D_];
__device__ float g_AB[B_ * N_ * 2 * HID_];     // per-node i-term(+b1) | j-term
__device__ float g_S[B_ * N_ * N_];
__device__ __align__(16) __nv_bfloat16 g_W1t_hi[NPAD * D_];   // W1c^T [n][k]
__device__ __align__(16) __nv_bfloat16 g_W1t_lo[NPAD * D_];
__device__ __align__(16) __nv_bfloat16 g_W2t_hi[NPAD * 256];  // W2^T [n][k], K zero-padded
__device__ __align__(16) __nv_bfloat16 g_W2t_lo[NPAD * 256];

// ---------------- helpers ----------------
__device__ __forceinline__ uint32_t smem_u32(const void* p) {
    uint32_t a;
    asm("{ .reg .u64 t; cvta.to.shared.u64 t, %1; cvt.u32.u64 %0, t; }" : "=r"(a) : "l"(p));
    return a;
}
__device__ __forceinline__ void cp16(uint32_t s, const __nv_bfloat16* g) {
    asm volatile("cp.async.cg.shared.global [%0], [%1], 16;"
                 :: "r"(s), "l"(__cvta_generic_to_global((const void*)g)));
}
#define CP_COMMIT() asm volatile("cp.async.commit_group;" ::: "memory")
#define CP_WAIT0()  asm volatile("cp.async.wait_group 0;" ::: "memory")

__device__ __forceinline__ void ldsm4(uint32_t& r0, uint32_t& r1, uint32_t& r2, uint32_t& r3,
                                      uint32_t addr) {
    asm volatile("ldmatrix.sync.aligned.m8n8.x4.shared.b16 {%0,%1,%2,%3}, [%4];"
                 : "=r"(r0), "=r"(r1), "=r"(r2), "=r"(r3) : "r"(addr));
}
__device__ __forceinline__ void mma16816(float* c,
        uint32_t a0, uint32_t a1, uint32_t a2, uint32_t a3, uint32_t b0, uint32_t b1) {
    asm volatile("mma.sync.aligned.m16n8k16.row.col.f32.bf16.bf16.f32 "
                 "{%0,%1,%2,%3}, {%4,%5,%6,%7}, {%8,%9}, {%0,%1,%2,%3};"
                 : "+f"(c[0]), "+f"(c[1]), "+f"(c[2]), "+f"(c[3])
                 : "r"(a0), "r"(a1), "r"(a2), "r"(a3), "r"(b0), "r"(b1));
}
// pack two fp32 -> bf16x2 hi word + residual lo word
__device__ __forceinline__ void split2(float a, float b, uint32_t& hi, uint32_t& lo) {
    __nv_bfloat162 h2 = __floats2bfloat162_rn(a, b);
    float ra = a - __bfloat162float(h2.x);
    float rb = b - __bfloat162float(h2.y);
    __nv_bfloat162 l2 = __floats2bfloat162_rn(ra, rb);
    hi = *reinterpret_cast<uint32_t*>(&h2);
    lo = *reinterpret_cast<uint32_t*>(&l2);
}

// ---------------- weight split/transpose precompute ----------------
__global__ void __launch_bounds__(256) prep_weights(const float* __restrict__ W1,
                                                    const float* __restrict__ W2) {
    int idx = blockIdx.x * 256 + threadIdx.x;
    if (idx < NPAD * D_) {
        int n = idx / D_, k = idx - n * D_;
        float v = (n < HID_) ? W1[(size_t)(2 * D_ + k) * HID_ + n] : 0.f;
        __nv_bfloat16 h = __float2bfloat16(v);
        g_W1t_hi[idx] = h;
        g_W1t_lo[idx] = __float2bfloat16(v - __bfloat162float(h));
    }
    if (idx < NPAD * 256) {
        int n = idx >> 8, k = idx & 255;
        float v = (n < HID_ && k < HID_) ? W2[(size_t)k * HID_ + n] : 0.f;
        __nv_bfloat16 h = __float2bfloat16(v);
        g_W2t_hi[idx] = h;
        g_W2t_lo[idx] = __float2bfloat16(v - __bfloat162float(h));
    }
}

// ---------------- Stage 1: gather + per-node W1a/W1b terms ----------------
__global__ void __launch_bounds__(256) stage1_kernel(
    const float* __restrict__ event_embed, const int* __restrict__ event_idx,
    const float* __restrict__ W1, const float* __restrict__ b1) {
    __shared__ float e[4][D_];
    int blk = blockIdx.x;
    int row0 = blk * 4;
    int b = row0 >> 8, n0 = row0 & 255;
    for (int rr = 0; rr < 4; rr++) {
        int t = event_idx[b * N_ + n0 + rr];
        const float* src = event_embed + ((size_t)b * T_ + t) * D_;
        float* dst = g_emb + (size_t)(b * N_ + n0 + rr) * D_;
        for (int d = threadIdx.x; d < D_; d += 256) {
            float v = src[d];
            e[rr][d] = v;
            dst[d] = v;
        }
    }
    __syncthreads();
    for (int h = threadIdx.x; h < 2 * HID_; h += 256) {
        const float* w;
        int col;
        float bias;
        if (h < HID_) { col = h;        w = W1;                     bias = b1[h]; }
        else          { col = h - HID_; w = W1 + (size_t)D_ * HID_; bias = 0.f; }
        float a0 = bias, a1 = bias, a2 = bias, a3 = bias;
        #pragma unroll 4
        for (int d = 0; d < D_; d++) {
            float wv = w[(size_t)d * HID_ + col];
            a0 = fmaf(e[0][d], wv, a0);
            a1 = fmaf(e[1][d], wv, a1);
            a2 = fmaf(e[2][d], wv, a2);
            a3 = fmaf(e[3][d], wv, a3);
        }
        size_t base = (size_t)(b * N_ + n0) * (2 * HID_) + h;
        g_AB[base] = a0;
        g_AB[base + 2 * HID_] = a1;
        g_AB[base + 4 * HID_] = a2;
        g_AB[base + 6 * HID_] = a3;
    }
}

// ---------------- Stage 2 device pieces ----------------
__device__ __forceinline__ void fillB(uint32_t sb, int bufOff,
        const __nv_bfloat16* __restrict__ srcH, const __nv_bfloat16* __restrict__ srcL,
        int stride, int k0, int tid) {
    for (int it = tid; it < 832; it += THREADS) {
        int n = it >> 2, u = it & 3;
        uint32_t d = sb + BB_OFF + bufOff + n * (SB * 2) + u * 16;
        const __nv_bfloat16* sh = srcH + (size_t)n * stride + k0 + u * 8;
        const __nv_bfloat16* sl = srcL + (size_t)n * stride + k0 + u * 8;
        cp16(d, sh);
        cp16(d + 16640, sl);
    }
}

__device__ __forceinline__ void fillA(char* smp, int bufOff, const float* __restrict__ embB,
        const int* iis, const int* jjs, int k0, int tid) {
    for (int it = tid; it < 512; it += THREADS) {
        int r = it >> 2, u = it & 3;
        const float* ei = embB + (size_t)iis[r] * D_ + k0 + u * 8;
        const float* ej = embB + (size_t)jjs[r] * D_ + k0 + u * 8;
        float4 x0 = *(const float4*)ei, x1 = *(const float4*)(ei + 4);
        float4 y0 = *(const float4*)ej, y1 = *(const float4*)(ej + 4);
        uint4 hv, lv;
        split2(x0.x * y0.x, x0.y * y0.y, hv.x, lv.x);
        split2(x0.z * y0.z, x0.w * y0.w, hv.y, lv.y);
        split2(x1.x * y1.x, x1.y * y1.y, hv.z, lv.z);
        split2(x1.z * y1.z, x1.w * y1.w, hv.w, lv.w);
        char* p = smp + AB_OFF + bufOff + r * (SA * 2) + u * 16;
        *(uint4*)p = hv;
        *(uint4*)(p + 10240) = lv;
    }
}

// layer-1 MMA on one K=32 chunk (A from A-buf, B from B-buf)
__device__ __forceinline__ void mmaChunk1(uint32_t sb, int bufA, int bufB,
        int w, int lane, float (&acc)[26][4]) {
    uint32_t grp = lane >> 3, lr = lane & 7;
    uint32_t arow = 16 * w + (grp & 1) * 8 + lr;
    uint32_t akoff = (grp >> 1) * 8;
    uint32_t brow = (grp >> 1) * 8 + lr;
    uint32_t bkoff = (grp & 1) * 8;
    #pragma unroll
    for (int ks = 0; ks < 2; ks++) {
        int kb = ks * 16;
        uint32_t aaddr = sb + AB_OFF + bufA + arow * (SA * 2) + (kb + akoff) * 2;
        uint32_t a0, a1, a2, a3, e0, e1, e2, e3;
        ldsm4(a0, a1, a2, a3, aaddr);
        ldsm4(e0, e1, e2, e3, aaddr + 10240);
        #pragma unroll
        for (int i = 0; i < 13; i++) {
            uint32_t baddr = sb + BB_OFF + bufB + (16 * i + brow) * (SB * 2) + (kb + bkoff) * 2;
            uint32_t b0, b1, b2r, b3r, f0, f1, f2, f3;
            ldsm4(b0, b1, b2r, b3r, baddr);
            ldsm4(f0, f1, f2, f3, baddr + 16640);
            mma16816(acc[2 * i],     a0, a1, a2, a3, b0, b1);
            mma16816(acc[2 * i],     a0, a1, a2, a3, f0, f1);
            mma16816(acc[2 * i],     e0, e1, e2, e3, b0, b1);
            mma16816(acc[2 * i + 1], a0, a1, a2, a3, b2r, b3r);
            mma16816(acc[2 * i + 1], a0, a1, a2, a3, f2, f3);
            mma16816(acc[2 * i + 1], e0, e1, e2, e3, b2r, b3r);
        }
    }
}

// layer-2 MMA: A from h1 smem (stride SH), B from B-buf; k0g = global k of chunk
__device__ __forceinline__ void mmaChunk2(uint32_t sb, int bufB, int k0g, int ksteps,
        int w, int lane, float (&acc)[26][4]) {
    uint32_t grp = lane >> 3, lr = lane & 7;
    uint32_t arow = 16 * w + (grp & 1) * 8 + lr;
    uint32_t akoff = (grp >> 1) * 8;
    uint32_t brow = (grp >> 1) * 8 + lr;
    uint32_t bkoff = (grp & 1) * 8;
    for (int ks = 0; ks < ksteps; ks++) {
        int kb = ks * 16;
        uint32_t aaddr = sb + H1H_OFF + arow * (SH * 2) + (k0g + kb + akoff) * 2;
        uint32_t a0, a1, a2, a3, e0, e1, e2, e3;
        ldsm4(a0, a1, a2, a3, aaddr);
        ldsm4(e0, e1, e2, e3, aaddr + (H1L_OFF - H1H_OFF));
        #pragma unroll
        for (int i = 0; i < 13; i++) {
            uint32_t baddr = sb + BB_OFF + bufB + (16 * i + brow) * (SB * 2) + (kb + bkoff) * 2;
            uint32_t b0, b1, b2r, b3r, f0, f1, f2, f3;
            ldsm4(b0, b1, b2r, b3r, baddr);
            ldsm4(f0, f1, f2, f3, baddr + 16640);
            mma16816(acc[2 * i],     a0, a1, a2, a3, b0, b1);
            mma16816(acc[2 * i],     a0, a1, a2, a3, f0, f1);
            mma16816(acc[2 * i],     e0, e1, e2, e3, b0, b1);
            mma16816(acc[2 * i + 1], a0, a1, a2, a3, b2r, b3r);
            mma16816(acc[2 * i + 1], a0, a1, a2, a3, f2, f3);
            mma16816(acc[2 * i + 1], e0, e1, e2, e3, b2r, b3r);
        }
    }
}

// ---------------- Stage 2 kernel ----------------
__global__ void __launch_bounds__(THREADS, 1) stage2_mma(
    const float* __restrict__ b2, const float* __restrict__ W3,
    const float* __restrict__ b3) {
    extern __shared__ char sm[];
    uint32_t sb = smem_u32(sm);
    int tid = threadIdx.x;
    int w = tid >> 5, lane = tid & 31;
    int b = blockIdx.y, p0 = blockIdx.x * MT;

    int* iis = (int*)(sm + EXT_OFF);
    int* jjs = (int*)(sm + EXT_OFF + 512);
    float* b2s = (float*)(sm + EXT_OFF + 1024);
    float* w3s = (float*)(sm + EXT_OFF + 1856);

    if (tid < MT) {
        int p = p0 + tid;
        int i = (int)((1.0 + sqrt(1.0 + 8.0 * (double)p)) * 0.5);
        while (i * (i - 1) / 2 > p) --i;
        while ((i + 1) * i / 2 <= p) ++i;
        iis[tid] = i;
        jjs[tid] = p - i * (i - 1) / 2;
    }
    for (int h = tid; h < NPAD; h += THREADS) {
        b2s[h] = (h < HID_) ? b2[h] : 0.f;
        w3s[h] = (h < HID_) ? W3[h] : 0.f;
    }
    __syncthreads();

    const int q = lane >> 2, e2c = (lane & 3) * 2;
    const int r0 = 16 * w + q, r1 = r0 + 8;
    const float* embB = g_emb + (size_t)b * N_ * D_;

    // seed layer-1 accumulators: A_i + B_j (b1 folded)
    float acc[26][4];
    {
        const float* Ai0 = g_AB + (size_t)(b * N_ + iis[r0]) * (2 * HID_);
        const float* Bj0 = g_AB + (size_t)(b * N_ + jjs[r0]) * (2 * HID_) + HID_;
        const float* Ai1 = g_AB + (size_t)(b * N_ + iis[r1]) * (2 * HID_);
        const float* Bj1 = g_AB + (size_t)(b * N_ + jjs[r1]) * (2 * HID_) + HID_;
        #pragma unroll
        for (int nt = 0; nt < 26; nt++) {
            int c = 8 * nt + e2c;
            acc[nt][0] = (c     < HID_) ? Ai0[c]     + Bj0[c]     : 0.f;
            acc[nt][1] = (c + 1 < HID_) ? Ai0[c + 1] + Bj0[c + 1] : 0.f;
            acc[nt][2] = (c     < HID_) ? Ai1[c]     + Bj1[c]     : 0.f;
            acc[nt][3] = (c + 1 < HID_) ? Ai1[c + 1] + Bj1[c + 1] : 0.f;
        }
    }

    // ---- Layer 1: 24 chunks of K=32, double-buffered ----
    fillB(sb, 0, g_W1t_hi, g_W1t_lo, D_, 0, tid);
    CP_COMMIT();
    fillA(sm, 0, embB, iis, jjs, 0, tid);
    CP_WAIT0();
    __syncthreads();
    for (int c = 0; c < 24; c++) {
        int nc = c + 1;
        if (nc < 24) {
            fillB(sb, (nc & 1) * BB_SZ, g_W1t_hi, g_W1t_lo, D_, nc * 32, tid);
            CP_COMMIT();
            fillA(sm, (nc & 1) * AB_SZ, embB, iis, jjs, nc * 32, tid);
        }
        mmaChunk1(sb, (c & 1) * AB_SZ, (c & 1) * BB_SZ, w, lane, acc);
        CP_WAIT0();
        __syncthreads();
    }

    // ---- relu/split h1 -> smem; reseed accumulators with b2 ----
    #pragma unroll
    for (int nt = 0; nt < 26; nt++) {
        int c = 8 * nt + e2c;
        uint32_t hw, lw;
        split2(fmaxf(acc[nt][0], 0.f), fmaxf(acc[nt][1], 0.f), hw, lw);
        *(uint32_t*)(sm + H1H_OFF + r0 * (SH * 2) + c * 2) = hw;
        *(uint32_t*)(sm + H1L_OFF + r0 * (SH * 2) + c * 2) = lw;
        split2(fmaxf(acc[nt][2], 0.f), fmaxf(acc[nt][3], 0.f), hw, lw);
        *(uint32_t*)(sm + H1H_OFF + r1 * (SH * 2) + c * 2) = hw;
        *(uint32_t*)(sm + H1L_OFF + r1 * (SH * 2) + c * 2) = lw;
        float bb0 = b2s[c], bb1 = b2s[c + 1];
        acc[nt][0] = bb0; acc[nt][1] = bb1; acc[nt][2] = bb0; acc[nt][3] = bb1;
    }
    __syncthreads();

    // ---- Layer 2: 7 chunks (last covers k 192..207 with 1 k-step) ----
    fillB(sb, 0, g_W2t_hi, g_W2t_lo, 256, 0, tid);
    CP_COMMIT();
    CP_WAIT0();
    __syncthreads();
    for (int c = 0; c < 7; c++) {
        int nc = c + 1;
        if (nc < 7) {
            fillB(sb, (nc & 1) * BB_SZ, g_W2t_hi, g_W2t_lo, 256, nc * 32, tid);
            CP_COMMIT();
        }
        mmaChunk2(sb, (c & 1) * BB_SZ, c * 32, (c == 6) ? 1 : 2, w, lane, acc);
        CP_WAIT0();
        __syncthreads();
    }

    // ---- Layer 3: s = relu(h2) . W3 + b3 ----
    float s0 = 0.f, s1 = 0.f;
    #pragma unroll
    for (int nt = 0; nt < 26; nt++) {
        int c = 8 * nt + e2c;
        float w0 = w3s[c], w1v = w3s[c + 1];
        s0 = fmaf(fmaxf(acc[nt][0], 0.f), w0, s0);
        s0 = fmaf(fmaxf(acc[nt][1], 0.f), w1v, s0);
        s1 = fmaf(fmaxf(acc[nt][2], 0.f), w0, s1);
        s1 = fmaf(fmaxf(acc[nt][3], 0.f), w1v, s1);
    }
    s0 += __shfl_xor_sync(0xffffffffu, s0, 1);
    s0 += __shfl_xor_sync(0xffffffffu, s0, 2);
    s1 += __shfl_xor_sync(0xffffffffu, s1, 1);
    s1 += __shfl_xor_sync(0xffffffffu, s1, 2);
    if ((lane & 3) == 0) {
        float bb3 = b3[0];
        g_S[(size_t)(b * N_ + iis[r0]) * N_ + jjs[r0]] = s0 + bb3;
        g_S[(size_t)(b * N_ + iis[r1]) * N_ + jjs[r1]] = s1 + bb3;
    }
}

// ---------------- Stage 3: masked row softmax ----------------
__global__ void __launch_bounds__(128) softmax_kernel(float* __restrict__ out) {
    int blk = blockIdx.x;
    int i = blk & 255;
    const float* srow = g_S + (size_t)blk * N_;
    float* orow = out + (size_t)blk * N_;
    __shared__ float redm[4], redz[4];
    int tid = threadIdx.x;

    float m = (tid == 0) ? 0.f : -INFINITY;
    for (int j = tid; j < i; j += 128) m = fmaxf(m, srow[j]);
    #pragma unroll
    for (int o = 16; o; o >>= 1) m = fmaxf(m, __shfl_xor_sync(0xffffffffu, m, o));
    if ((tid & 31) == 0) redm[tid >> 5] = m;
    __syncthreads();
    m = fmaxf(fmaxf(redm[0], redm[1]), fmaxf(redm[2], redm[3]));

    float z = (tid == 0) ? expf(-m) : 0.f;
    for (int j = tid; j < i; j += 128) z += expf(srow[j] - m);
    #pragma unroll
    for (int o = 16; o; o >>= 1) z += __shfl_xor_sync(0xffffffffu, z, o);
    if ((tid & 31) == 0) redz[tid >> 5] = z;
    __syncthreads();
    z = redz[0] + redz[1] + redz[2] + redz[3];
    float invz = 1.f / z;

    for (int j = tid; j < N_; j += 128) {
        float o_;
        if (j < i)       o_ = expf(srow[j] - m) * invz;
        else if (j == i) o_ = expf(-m) * invz;
        else             o_ = -1000.0f;
        orow[j] = o_;
    }
}

// ---------------- launch ----------------
extern "C" void kernel_launch(void* const* d_in, const int* in_sizes, int n_in,
                              void* d_out, int out_size) {
    (void)in_sizes; (void)n_in; (void)out_size;
    const float* event_embed = (const float*)d_in[0];
    const int*   event_idx   = (const int*)d_in[1];
    const float* W1 = (const float*)d_in[2];
    const float* b1 = (const float*)d_in[3];
    const float* W2 = (const float*)d_in[4];
    const float* b2 = (const float*)d_in[5];
    const float* W3 = (const float*)d_in[6];
    const float* b3 = (const float*)d_in[7];
    float* out = (float*)d_out;

    cudaFuncSetAttribute(stage2_mma, cudaFuncAttributeMaxDynamicSharedMemorySize, SMEM_TOTAL);

    prep_weights<<<(NPAD * D_ + 255) / 256, 256>>>(W1, W2);
    stage1_kernel<<<B_ * N_ / 4, 256>>>(event_embed, event_idx, W1, b1);

    dim3 grid2(P_ / MT, B_);
    stage2_mma<<<grid2, THREADS, SMEM_TOTAL>>>(b2, W3, b3);

    softmax_kernel<<<B_ * N_, 128>>>(out);
}

// round 4
// speedup vs baseline: 4.3988x; 1.6265x over previous
#include <cuda_runtime.h>
#include <cuda_bf16.h>
#include <cstdint>
#include <cmath>

// ---------------- problem constants ----------------
#define B_   4
#define T_   4096
#define D_   768
#define N_   256
#define HID_ 200
#define P_   32640         // N*(N-1)/2
#define NPAD 208
#define MT   128           // pairs per CTA
#define THREADS 256

// ---------------- SMEM layout (stage 2) ----------------
#define BB_OFF   0
#define BB_SZ    16640     // per buf: B[208][40] bf16
#define AB_OFF   33280
#define AB_SZ    10240     // per buf: A[128][40] bf16
#define H1_OFF   33280     // h1 [128][216] bf16 (55296) — overlaps A bufs (phase-disjoint)
#define EXT_OFF  88576     // iis(512) jjs(512) b2s(832) w3s(832)
#define SMEM_TOTAL 91264
#define SA 40              // A tile stride (bf16 elems) -> 80B, ldmatrix conflict-free
#define SB 40
#define SH 216             // h1 stride -> 432B, conflict-free

// ---------------- scratch (device globals) ----------------
__device__ __align__(16) float g_emb[B_ * N_ * D_];
__device__ float g_AB[B_ * N_ * 2 * HID_];     // per-node i-term(+b1) | j-term
__device__ float g_S[B_ * N_ * N_];
__device__ __align__(16) __nv_bfloat16 g_W1t[NPAD * D_];   // W1c^T [n][k] bf16
__device__ __align__(16) __nv_bfloat16 g_W2t[NPAD * 256];  // W2^T [n][k] bf16, K zero-padded

// ---------------- helpers ----------------
__device__ __forceinline__ uint32_t smem_u32(const void* p) {
    uint32_t a;
    asm("{ .reg .u64 t; cvta.to.shared.u64 t, %1; cvt.u32.u64 %0, t; }" : "=r"(a) : "l"(p));
    return a;
}
__device__ __forceinline__ void cp16(uint32_t s, const __nv_bfloat16* g) {
    asm volatile("cp.async.cg.shared.global [%0], [%1], 16;"
                 :: "r"(s), "l"(__cvta_generic_to_global((const void*)g)));
}
#define CP_COMMIT() asm volatile("cp.async.commit_group;" ::: "memory")
#define CP_WAIT0()  asm volatile("cp.async.wait_group 0;" ::: "memory")

__device__ __forceinline__ void ldsm4(uint32_t& r0, uint32_t& r1, uint32_t& r2, uint32_t& r3,
                                      uint32_t addr) {
    asm volatile("ldmatrix.sync.aligned.m8n8.x4.shared.b16 {%0,%1,%2,%3}, [%4];"
                 : "=r"(r0), "=r"(r1), "=r"(r2), "=r"(r3) : "r"(addr));
}
__device__ __forceinline__ void mma16816(float* c,
        uint32_t a0, uint32_t a1, uint32_t a2, uint32_t a3, uint32_t b0, uint32_t b1) {
    asm volatile("mma.sync.aligned.m16n8k16.row.col.f32.bf16.bf16.f32 "
                 "{%0,%1,%2,%3}, {%4,%5,%6,%7}, {%8,%9}, {%0,%1,%2,%3};"
                 : "+f"(c[0]), "+f"(c[1]), "+f"(c[2]), "+f"(c[3])
                 : "r"(a0), "r"(a1), "r"(a2), "r"(a3), "r"(b0), "r"(b1));
}
__device__ __forceinline__ uint32_t packbf2(float a, float b) {
    __nv_bfloat162 h2 = __floats2bfloat162_rn(a, b);
    return *reinterpret_cast<uint32_t*>(&h2);
}

// ---------------- weight transpose/convert precompute ----------------
__global__ void __launch_bounds__(256) prep_weights(const float* __restrict__ W1,
                                                    const float* __restrict__ W2) {
    int idx = blockIdx.x * 256 + threadIdx.x;
    if (idx < NPAD * D_) {
        int n = idx / D_, k = idx - n * D_;
        float v = (n < HID_) ? W1[(size_t)(2 * D_ + k) * HID_ + n] : 0.f;
        g_W1t[idx] = __float2bfloat16(v);
    }
    if (idx < NPAD * 256) {
        int n = idx >> 8, k = idx & 255;
        float v = (n < HID_ && k < HID_) ? W2[(size_t)k * HID_ + n] : 0.f;
        g_W2t[idx] = __float2bfloat16(v);
    }
}

// ---------------- Stage 1: gather + per-node W1a/W1b terms ----------------
__global__ void __launch_bounds__(256) stage1_kernel(
    const float* __restrict__ event_embed, const int* __restrict__ event_idx,
    const float* __restrict__ W1, const float* __restrict__ b1) {
    __shared__ float e[4][D_];
    int blk = blockIdx.x;
    int row0 = blk * 4;
    int b = row0 >> 8, n0 = row0 & 255;
    for (int rr = 0; rr < 4; rr++) {
        int t = event_idx[b * N_ + n0 + rr];
        const float* src = event_embed + ((size_t)b * T_ + t) * D_;
        float* dst = g_emb + (size_t)(b * N_ + n0 + rr) * D_;
        for (int d = threadIdx.x; d < D_; d += 256) {
            float v = src[d];
            e[rr][d] = v;
            dst[d] = v;
        }
    }
    __syncthreads();
    for (int h = threadIdx.x; h < 2 * HID_; h += 256) {
        const float* w;
        int col;
        float bias;
        if (h < HID_) { col = h;        w = W1;                     bias = b1[h]; }
        else          { col = h - HID_; w = W1 + (size_t)D_ * HID_; bias = 0.f; }
        float a0 = bias, a1 = bias, a2 = bias, a3 = bias;
        #pragma unroll 4
        for (int d = 0; d < D_; d++) {
            float wv = w[(size_t)d * HID_ + col];
            a0 = fmaf(e[0][d], wv, a0);
            a1 = fmaf(e[1][d], wv, a1);
            a2 = fmaf(e[2][d], wv, a2);
            a3 = fmaf(e[3][d], wv, a3);
        }
        size_t base = (size_t)(b * N_ + n0) * (2 * HID_) + h;
        g_AB[base] = a0;
        g_AB[base + 2 * HID_] = a1;
        g_AB[base + 4 * HID_] = a2;
        g_AB[base + 6 * HID_] = a3;
    }
}

// ---------------- Stage 2 device pieces ----------------
__device__ __forceinline__ void fillB(uint32_t sb, int bufOff,
        const __nv_bfloat16* __restrict__ src, int stride, int k0, int tid) {
    for (int it = tid; it < 832; it += THREADS) {
        int n = it >> 2, u = it & 3;
        cp16(sb + BB_OFF + bufOff + n * (SB * 2) + u * 16,
             src + (size_t)n * stride + k0 + u * 8);
    }
}

__device__ __forceinline__ void fillA(char* smp, int bufOff, const float* __restrict__ embB,
        const int* iis, const int* jjs, int k0, int tid) {
    for (int it = tid; it < 512; it += THREADS) {
        int r = it >> 2, u = it & 3;
        const float* ei = embB + (size_t)iis[r] * D_ + k0 + u * 8;
        const float* ej = embB + (size_t)jjs[r] * D_ + k0 + u * 8;
        float4 x0 = *(const float4*)ei, x1 = *(const float4*)(ei + 4);
        float4 y0 = *(const float4*)ej, y1 = *(const float4*)(ej + 4);
        uint4 hv;
        hv.x = packbf2(x0.x * y0.x, x0.y * y0.y);
        hv.y = packbf2(x0.z * y0.z, x0.w * y0.w);
        hv.z = packbf2(x1.x * y1.x, x1.y * y1.y);
        hv.w = packbf2(x1.z * y1.z, x1.w * y1.w);
        *(uint4*)(smp + AB_OFF + bufOff + r * (SA * 2) + u * 16) = hv;
    }
}

// layer-1 MMA on one K=32 chunk
__device__ __forceinline__ void mmaChunk1(uint32_t sb, int bufA, int bufB,
        int w, int lane, float (&acc)[26][4]) {
    uint32_t grp = lane >> 3, lr = lane & 7;
    uint32_t arow = 16 * w + (grp & 1) * 8 + lr;
    uint32_t akoff = (grp >> 1) * 8;
    uint32_t brow = (grp >> 1) * 8 + lr;
    uint32_t bkoff = (grp & 1) * 8;
    #pragma unroll
    for (int ks = 0; ks < 2; ks++) {
        int kb = ks * 16;
        uint32_t a0, a1, a2, a3;
        ldsm4(a0, a1, a2, a3, sb + AB_OFF + bufA + arow * (SA * 2) + (kb + akoff) * 2);
        #pragma unroll
        for (int i = 0; i < 13; i++) {
            uint32_t b0, b1, b2r, b3r;
            ldsm4(b0, b1, b2r, b3r,
                  sb + BB_OFF + bufB + (16 * i + brow) * (SB * 2) + (kb + bkoff) * 2);
            mma16816(acc[2 * i],     a0, a1, a2, a3, b0, b1);
            mma16816(acc[2 * i + 1], a0, a1, a2, a3, b2r, b3r);
        }
    }
}

// layer-2 MMA: A from h1 smem
__device__ __forceinline__ void mmaChunk2(uint32_t sb, int bufB, int k0g, int ksteps,
        int w, int lane, float (&acc)[26][4]) {
    uint32_t grp = lane >> 3, lr = lane & 7;
    uint32_t arow = 16 * w + (grp & 1) * 8 + lr;
    uint32_t akoff = (grp >> 1) * 8;
    uint32_t brow = (grp >> 1) * 8 + lr;
    uint32_t bkoff = (grp & 1) * 8;
    for (int ks = 0; ks < ksteps; ks++) {
        int kb = ks * 16;
        uint32_t a0, a1, a2, a3;
        ldsm4(a0, a1, a2, a3, sb + H1_OFF + arow * (SH * 2) + (k0g + kb + akoff) * 2);
        #pragma unroll
        for (int i = 0; i < 13; i++) {
            uint32_t b0, b1, b2r, b3r;
            ldsm4(b0, b1, b2r, b3r,
                  sb + BB_OFF + bufB + (16 * i + brow) * (SB * 2) + (kb + bkoff) * 2);
            mma16816(acc[2 * i],     a0, a1, a2, a3, b0, b1);
            mma16816(acc[2 * i + 1], a0, a1, a2, a3, b2r, b3r);
        }
    }
}

// ---------------- Stage 2 kernel ----------------
__global__ void __launch_bounds__(THREADS, 1) stage2_mma(
    const float* __restrict__ b2, const float* __restrict__ W3,
    const float* __restrict__ b3) {
    extern __shared__ char sm[];
    uint32_t sb = smem_u32(sm);
    int tid = threadIdx.x;
    int w = tid >> 5, lane = tid & 31;
    int b = blockIdx.y, p0 = blockIdx.x * MT;

    int* iis = (int*)(sm + EXT_OFF);
    int* jjs = (int*)(sm + EXT_OFF + 512);
    float* b2s = (float*)(sm + EXT_OFF + 1024);
    float* w3s = (float*)(sm + EXT_OFF + 1856);

    if (tid < MT) {
        int p = p0 + tid;
        int i = (int)((1.0 + sqrt(1.0 + 8.0 * (double)p)) * 0.5);
        while (i * (i - 1) / 2 > p) --i;
        while ((i + 1) * i / 2 <= p) ++i;
        iis[tid] = i;
        jjs[tid] = p - i * (i - 1) / 2;
    }
    for (int h = tid; h < NPAD; h += THREADS) {
        b2s[h] = (h < HID_) ? b2[h] : 0.f;
        w3s[h] = (h < HID_) ? W3[h] : 0.f;
    }
    __syncthreads();

    const int q = lane >> 2, e2c = (lane & 3) * 2;
    const int r0 = 16 * w + q, r1 = r0 + 8;
    const float* embB = g_emb + (size_t)b * N_ * D_;

    // seed layer-1 accumulators: A_i + B_j (b1 folded)
    float acc[26][4];
    {
        const float* Ai0 = g_AB + (size_t)(b * N_ + iis[r0]) * (2 * HID_);
        const float* Bj0 = g_AB + (size_t)(b * N_ + jjs[r0]) * (2 * HID_) + HID_;
        const float* Ai1 = g_AB + (size_t)(b * N_ + iis[r1]) * (2 * HID_);
        const float* Bj1 = g_AB + (size_t)(b * N_ + jjs[r1]) * (2 * HID_) + HID_;
        #pragma unroll
        for (int nt = 0; nt < 26; nt++) {
            int c = 8 * nt + e2c;
            acc[nt][0] = (c     < HID_) ? Ai0[c]     + Bj0[c]     : 0.f;
            acc[nt][1] = (c + 1 < HID_) ? Ai0[c + 1] + Bj0[c + 1] : 0.f;
            acc[nt][2] = (c     < HID_) ? Ai1[c]     + Bj1[c]     : 0.f;
            acc[nt][3] = (c + 1 < HID_) ? Ai1[c + 1] + Bj1[c + 1] : 0.f;
        }
    }

    // ---- Layer 1: 24 chunks of K=32, double-buffered ----
    fillB(sb, 0, g_W1t, D_, 0, tid);
    CP_COMMIT();
    fillA(sm, 0, embB, iis, jjs, 0, tid);
    CP_WAIT0();
    __syncthreads();
    for (int c = 0; c < 24; c++) {
        int nc = c + 1;
        if (nc < 24) {
            fillB(sb, (nc & 1) * BB_SZ, g_W1t, D_, nc * 32, tid);
            CP_COMMIT();
            fillA(sm, (nc & 1) * AB_SZ, embB, iis, jjs, nc * 32, tid);
        }
        mmaChunk1(sb, (c & 1) * AB_SZ, (c & 1) * BB_SZ, w, lane, acc);
        CP_WAIT0();
        __syncthreads();
    }

    // ---- relu h1 -> smem (bf16); reseed accumulators with b2 ----
    #pragma unroll
    for (int nt = 0; nt < 26; nt++) {
        int c = 8 * nt + e2c;
        *(uint32_t*)(sm + H1_OFF + r0 * (SH * 2) + c * 2) =
            packbf2(fmaxf(acc[nt][0], 0.f), fmaxf(acc[nt][1], 0.f));
        *(uint32_t*)(sm + H1_OFF + r1 * (SH * 2) + c * 2) =
            packbf2(fmaxf(acc[nt][2], 0.f), fmaxf(acc[nt][3], 0.f));
        float bb0 = b2s[c], bb1 = b2s[c + 1];
        acc[nt][0] = bb0; acc[nt][1] = bb1; acc[nt][2] = bb0; acc[nt][3] = bb1;
    }
    __syncthreads();

    // ---- Layer 2: 7 chunks (last covers k 192..207 with 1 k-step) ----
    fillB(sb, 0, g_W2t, 256, 0, tid);
    CP_COMMIT();
    CP_WAIT0();
    __syncthreads();
    for (int c = 0; c < 7; c++) {
        int nc = c + 1;
        if (nc < 7) {
            fillB(sb, (nc & 1) * BB_SZ, g_W2t, 256, nc * 32, tid);
            CP_COMMIT();
        }
        mmaChunk2(sb, (c & 1) * BB_SZ, c * 32, (c == 6) ? 1 : 2, w, lane, acc);
        CP_WAIT0();
        __syncthreads();
    }

    // ---- Layer 3: s = relu(h2) . W3 + b3 ----
    float s0 = 0.f, s1 = 0.f;
    #pragma unroll
    for (int nt = 0; nt < 26; nt++) {
        int c = 8 * nt + e2c;
        float w0 = w3s[c], w1v = w3s[c + 1];
        s0 = fmaf(fmaxf(acc[nt][0], 0.f), w0, s0);
        s0 = fmaf(fmaxf(acc[nt][1], 0.f), w1v, s0);
        s1 = fmaf(fmaxf(acc[nt][2], 0.f), w0, s1);
        s1 = fmaf(fmaxf(acc[nt][3], 0.f), w1v, s1);
    }
    s0 += __shfl_xor_sync(0xffffffffu, s0, 1);
    s0 += __shfl_xor_sync(0xffffffffu, s0, 2);
    s1 += __shfl_xor_sync(0xffffffffu, s1, 1);
    s1 += __shfl_xor_sync(0xffffffffu, s1, 2);
    if ((lane & 3) == 0) {
        float bb3 = b3[0];
        g_S[(size_t)(b * N_ + iis[r0]) * N_ + jjs[r0]] = s0 + bb3;
        g_S[(size_t)(b * N_ + iis[r1]) * N_ + jjs[r1]] = s1 + bb3;
    }
}

// ---------------- Stage 3: masked row softmax ----------------
__global__ void __launch_bounds__(128) softmax_kernel(float* __restrict__ out) {
    int blk = blockIdx.x;
    int i = blk & 255;
    const float* srow = g_S + (size_t)blk * N_;
    float* orow = out + (size_t)blk * N_;
    __shared__ float redm[4], redz[4];
    int tid = threadIdx.x;

    float m = (tid == 0) ? 0.f : -INFINITY;
    for (int j = tid; j < i; j += 128) m = fmaxf(m, srow[j]);
    #pragma unroll
    for (int o = 16; o; o >>= 1) m = fmaxf(m, __shfl_xor_sync(0xffffffffu, m, o));
    if ((tid & 31) == 0) redm[tid >> 5] = m;
    __syncthreads();
    m = fmaxf(fmaxf(redm[0], redm[1]), fmaxf(redm[2], redm[3]));

    float z = (tid == 0) ? expf(-m) : 0.f;
    for (int j = tid; j < i; j += 128) z += expf(srow[j] - m);
    #pragma unroll
    for (int o = 16; o; o >>= 1) z += __shfl_xor_sync(0xffffffffu, z, o);
    if ((tid & 31) == 0) redz[tid >> 5] = z;
    __syncthreads();
    z = redz[0] + redz[1] + redz[2] + redz[3];
    float invz = 1.f / z;

    for (int j = tid; j < N_; j += 128) {
        float o_;
        if (j < i)       o_ = expf(srow[j] - m) * invz;
        else if (j == i) o_ = expf(-m) * invz;
        else             o_ = -1000.0f;
        orow[j] = o_;
    }
}

// ---------------- launch ----------------
extern "C" void kernel_launch(void* const* d_in, const int* in_sizes, int n_in,
                              void* d_out, int out_size) {
    (void)in_sizes; (void)n_in; (void)out_size;
    const float* event_embed = (const float*)d_in[0];
    const int*   event_idx   = (const int*)d_in[1];
    const float* W1 = (const float*)d_in[2];
    const float* b1 = (const float*)d_in[3];
    const float* W2 = (const float*)d_in[4];
    const float* b2 = (const float*)d_in[5];
    const float* W3 = (const float*)d_in[6];
    const float* b3 = (const float*)d_in[7];
    float* out = (float*)d_out;

    cudaFuncSetAttribute(stage2_mma, cudaFuncAttributeMaxDynamicSharedMemorySize, SMEM_TOTAL);

    prep_weights<<<(NPAD * D_ + 255) / 256, 256>>>(W1, W2);
    stage1_kernel<<<B_ * N_ / 4, 256>>>(event_embed, event_idx, W1, b1);

    dim3 grid2(P_ / MT, B_);
    stage2_mma<<<grid2, THREADS, SMEM_TOTAL>>>(b2, W3, b3);

    softmax_kernel<<<B_ * N_, 128>>>(out);
}

// round 5
// speedup vs baseline: 4.6102x; 1.0481x over previous
#include <cuda_runtime.h>
#include <cuda_bf16.h>
#include <cstdint>
#include <cmath>

// ---------------- problem constants ----------------
#define B_   4
#define T_   4096
#define D_   768
#define N_   256
#define HID_ 200
#define P_   32640         // N*(N-1)/2 = 170 * 192
#define NPAD 208
#define MT   192           // pairs per CTA (12 warps x 16 rows)
#define THREADS 384

// ---------------- SMEM layout (stage 2) ----------------
#define BB_OFF   0
#define BB_SZ    29952     // per buf: B[208][72] bf16 (layer1 K=64 + pad)
#define AB_OFF   59904
#define AB_SZ    27648     // per buf: A[192][72] bf16
#define H1_OFF   59904     // h1 [192][216] bf16 (82944) — overlaps A bufs (phase-disjoint)
#define EXT_OFF  142848    // iis(768) jjs(768) b2s(832) w3s(832)
#define SMEM_TOTAL 146048
#define SAL1 72            // layer1 A/B stride (144B rows) — ldsm conflict-free
#define SB2  40            // layer2 B stride (80B rows)
#define SH   216           // h1 stride (432B rows)

// ---------------- scratch (device globals) ----------------
__device__ __align__(16) __nv_bfloat16 g_embh[B_ * N_ * D_];
__device__ float g_AB[B_ * N_ * 2 * HID_];     // per-node i-term(+b1) | j-term
__device__ float g_S[B_ * N_ * N_];
__device__ __align__(16) __nv_bfloat16 g_W1t[NPAD * D_];   // W1c^T [n][k] bf16
__device__ __align__(16) __nv_bfloat16 g_W2t[NPAD * 256];  // W2^T [n][k] bf16, K padded

// ---------------- helpers ----------------
__device__ __forceinline__ uint32_t smem_u32(const void* p) {
    uint32_t a;
    asm("{ .reg .u64 t; cvta.to.shared.u64 t, %1; cvt.u32.u64 %0, t; }" : "=r"(a) : "l"(p));
    return a;
}
__device__ __forceinline__ void cp16(uint32_t s, const __nv_bfloat16* g) {
    asm volatile("cp.async.cg.shared.global [%0], [%1], 16;"
                 :: "r"(s), "l"(__cvta_generic_to_global((const void*)g)));
}
#define CP_COMMIT() asm volatile("cp.async.commit_group;" ::: "memory")
#define CP_WAIT0()  asm volatile("cp.async.wait_group 0;" ::: "memory")

__device__ __forceinline__ void ldsm4(uint32_t& r0, uint32_t& r1, uint32_t& r2, uint32_t& r3,
                                      uint32_t addr) {
    asm volatile("ldmatrix.sync.aligned.m8n8.x4.shared.b16 {%0,%1,%2,%3}, [%4];"
                 : "=r"(r0), "=r"(r1), "=r"(r2), "=r"(r3) : "r"(addr));
}
__device__ __forceinline__ void mma16816(float* c,
        uint32_t a0, uint32_t a1, uint32_t a2, uint32_t a3, uint32_t b0, uint32_t b1) {
    asm volatile("mma.sync.aligned.m16n8k16.row.col.f32.bf16.bf16.f32 "
                 "{%0,%1,%2,%3}, {%4,%5,%6,%7}, {%8,%9}, {%0,%1,%2,%3};"
                 : "+f"(c[0]), "+f"(c[1]), "+f"(c[2]), "+f"(c[3])
                 : "r"(a0), "r"(a1), "r"(a2), "r"(a3), "r"(b0), "r"(b1));
}
__device__ __forceinline__ uint32_t packbf2(float a, float b) {
    __nv_bfloat162 h2 = __floats2bfloat162_rn(a, b);
    return *reinterpret_cast<uint32_t*>(&h2);
}

// ---------------- weight transpose/convert precompute ----------------
__global__ void __launch_bounds__(256) prep_weights(const float* __restrict__ W1,
                                                    const float* __restrict__ W2) {
    int idx = blockIdx.x * 256 + threadIdx.x;
    if (idx < NPAD * D_) {
        int n = idx / D_, k = idx - n * D_;
        float v = (n < HID_) ? W1[(size_t)(2 * D_ + k) * HID_ + n] : 0.f;
        g_W1t[idx] = __float2bfloat16(v);
    }
    if (idx < NPAD * 256) {
        int n = idx >> 8, k = idx & 255;
        float v = (n < HID_ && k < HID_) ? W2[(size_t)k * HID_ + n] : 0.f;
        g_W2t[idx] = __float2bfloat16(v);
    }
}

// ---------------- Stage 1: gather + per-node W1a/W1b terms (8 rows/block) ----------------
__global__ void __launch_bounds__(256) stage1_kernel(
    const float* __restrict__ event_embed, const int* __restrict__ event_idx,
    const float* __restrict__ W1, const float* __restrict__ b1) {
    __shared__ float e[8][D_];
    int row0 = blockIdx.x * 8;
    int b = row0 >> 8, n0 = row0 & 255;
    for (int rr = 0; rr < 8; rr++) {
        int t = event_idx[b * N_ + n0 + rr];
        const float* src = event_embed + ((size_t)b * T_ + t) * D_;
        __nv_bfloat16* dsth = g_embh + (size_t)(b * N_ + n0 + rr) * D_;
        for (int d = threadIdx.x; d < D_; d += 256) {
            float v = src[d];
            e[rr][d] = v;
            dsth[d] = __float2bfloat16(v);
        }
    }
    __syncthreads();
    for (int h = threadIdx.x; h < 2 * HID_; h += 256) {
        const float* w;
        int col;
        float bias;
        if (h < HID_) { col = h;        w = W1;                     bias = b1[h]; }
        else          { col = h - HID_; w = W1 + (size_t)D_ * HID_; bias = 0.f; }
        float a[8];
        #pragma unroll
        for (int r = 0; r < 8; r++) a[r] = bias;
        #pragma unroll 4
        for (int d = 0; d < D_; d++) {
            float wv = w[(size_t)d * HID_ + col];
            #pragma unroll
            for (int r = 0; r < 8; r++) a[r] = fmaf(e[r][d], wv, a[r]);
        }
        size_t base = (size_t)(b * N_ + n0) * (2 * HID_) + h;
        #pragma unroll
        for (int r = 0; r < 8; r++) g_AB[base + (size_t)r * 2 * HID_] = a[r];
    }
}

// ---------------- Stage 2 device pieces ----------------
// layer-1 B fill: [208][64] bf16, stride 72
__device__ __forceinline__ void fillB1(uint32_t sb, int bufOff,
        const __nv_bfloat16* __restrict__ src, int k0, int tid) {
    for (int it = tid; it < 1664; it += THREADS) {
        int n = it >> 3, u = it & 7;
        cp16(sb + BB_OFF + bufOff + n * (SAL1 * 2) + u * 16,
             src + (size_t)n * D_ + k0 + u * 8);
    }
}
// layer-2 B fill: [208][32] bf16, stride 40
__device__ __forceinline__ void fillB2(uint32_t sb, int bufOff,
        const __nv_bfloat16* __restrict__ src, int k0, int tid) {
    for (int it = tid; it < 832; it += THREADS) {
        int n = it >> 2, u = it & 3;
        cp16(sb + BB_OFF + bufOff + n * (SB2 * 2) + u * 16,
             src + (size_t)n * 256 + k0 + u * 8);
    }
}
// A fill: bf16 pair products, [192][64], stride 72
__device__ __forceinline__ void fillA(char* smp, int bufOff,
        const __nv_bfloat16* __restrict__ embB,
        const int* iis, const int* jjs, int k0, int tid) {
    for (int it = tid; it < 1536; it += THREADS) {
        int r = it >> 3, u = it & 7;
        const uint4 vi = *(const uint4*)(embB + (size_t)iis[r] * D_ + k0 + u * 8);
        const uint4 vj = *(const uint4*)(embB + (size_t)jjs[r] * D_ + k0 + u * 8);
        const __nv_bfloat162* pi = (const __nv_bfloat162*)&vi;
        const __nv_bfloat162* pj = (const __nv_bfloat162*)&vj;
        uint4 pv;
        __nv_bfloat162 m0 = __hmul2(pi[0], pj[0]);
        __nv_bfloat162 m1 = __hmul2(pi[1], pj[1]);
        __nv_bfloat162 m2 = __hmul2(pi[2], pj[2]);
        __nv_bfloat162 m3 = __hmul2(pi[3], pj[3]);
        pv.x = *reinterpret_cast<uint32_t*>(&m0);
        pv.y = *reinterpret_cast<uint32_t*>(&m1);
        pv.z = *reinterpret_cast<uint32_t*>(&m2);
        pv.w = *reinterpret_cast<uint32_t*>(&m3);
        *(uint4*)(smp + AB_OFF + bufOff + r * (SAL1 * 2) + u * 16) = pv;
    }
}

// layer-1 MMA on one K=64 chunk
__device__ __forceinline__ void mmaChunk1(uint32_t sb, int bufA, int bufB,
        int w, int lane, float (&acc)[26][4]) {
    uint32_t grp = lane >> 3, lr = lane & 7;
    uint32_t arow = 16 * w + (grp & 1) * 8 + lr;
    uint32_t akoff = (grp >> 1) * 8;
    uint32_t brow = (grp >> 1) * 8 + lr;
    uint32_t bkoff = (grp & 1) * 8;
    uint32_t abase = sb + AB_OFF + bufA + arow * (SAL1 * 2);
    uint32_t bbase = sb + BB_OFF + bufB + brow * (SAL1 * 2);
    #pragma unroll
    for (int ks = 0; ks < 4; ks++) {
        int kb = ks * 16;
        uint32_t a0, a1, a2, a3;
        ldsm4(a0, a1, a2, a3, abase + (kb + akoff) * 2);
        #pragma unroll
        for (int i = 0; i < 13; i++) {
            uint32_t b0, b1, b2r, b3r;
            ldsm4(b0, b1, b2r, b3r, bbase + (16 * i) * (SAL1 * 2) + (kb + bkoff) * 2);
            mma16816(acc[2 * i],     a0, a1, a2, a3, b0, b1);
            mma16816(acc[2 * i + 1], a0, a1, a2, a3, b2r, b3r);
        }
    }
}

// layer-2 MMA: A from h1 smem (stride SH), B stride 40
__device__ __forceinline__ void mmaChunk2(uint32_t sb, int bufB, int k0g, int ksteps,
        int w, int lane, float (&acc)[26][4]) {
    uint32_t grp = lane >> 3, lr = lane & 7;
    uint32_t arow = 16 * w + (grp & 1) * 8 + lr;
    uint32_t akoff = (grp >> 1) * 8;
    uint32_t brow = (grp >> 1) * 8 + lr;
    uint32_t bkoff = (grp & 1) * 8;
    uint32_t abase = sb + H1_OFF + arow * (SH * 2);
    uint32_t bbase = sb + BB_OFF + bufB + brow * (SB2 * 2);
    for (int ks = 0; ks < ksteps; ks++) {
        int kb = ks * 16;
        uint32_t a0, a1, a2, a3;
        ldsm4(a0, a1, a2, a3, abase + (k0g + kb + akoff) * 2);
        #pragma unroll
        for (int i = 0; i < 13; i++) {
            uint32_t b0, b1, b2r, b3r;
            ldsm4(b0, b1, b2r, b3r, bbase + (16 * i) * (SB2 * 2) + (kb + bkoff) * 2);
            mma16816(acc[2 * i],     a0, a1, a2, a3, b0, b1);
            mma16816(acc[2 * i + 1], a0, a1, a2, a3, b2r, b3r);
        }
    }
}

// ---------------- Stage 2 kernel ----------------
__global__ void __launch_bounds__(THREADS, 1) stage2_mma(
    const float* __restrict__ b2, const float* __restrict__ W3,
    const float* __restrict__ b3) {
    extern __shared__ char sm[];
    uint32_t sb = smem_u32(sm);
    int tid = threadIdx.x;
    int w = tid >> 5, lane = tid & 31;
    int b = blockIdx.y, p0 = blockIdx.x * MT;

    int* iis = (int*)(sm + EXT_OFF);
    int* jjs = (int*)(sm + EXT_OFF + 768);
    float* b2s = (float*)(sm + EXT_OFF + 1536);
    float* w3s = (float*)(sm + EXT_OFF + 2368);

    if (tid < MT) {
        int p = p0 + tid;
        int i = (int)((1.0 + sqrt(1.0 + 8.0 * (double)p)) * 0.5);
        while (i * (i - 1) / 2 > p) --i;
        while ((i + 1) * i / 2 <= p) ++i;
        iis[tid] = i;
        jjs[tid] = p - i * (i - 1) / 2;
    }
    for (int h = tid; h < NPAD; h += THREADS) {
        b2s[h] = (h < HID_) ? b2[h] : 0.f;
        w3s[h] = (h < HID_) ? W3[h] : 0.f;
    }
    __syncthreads();

    const int q = lane >> 2, e2c = (lane & 3) * 2;
    const int r0 = 16 * w + q, r1 = r0 + 8;
    const __nv_bfloat16* embB = g_embh + (size_t)b * N_ * D_;

    // seed layer-1 accumulators: A_i + B_j (b1 folded)
    float acc[26][4];
    {
        const float* Ai0 = g_AB + (size_t)(b * N_ + iis[r0]) * (2 * HID_);
        const float* Bj0 = g_AB + (size_t)(b * N_ + jjs[r0]) * (2 * HID_) + HID_;
        const float* Ai1 = g_AB + (size_t)(b * N_ + iis[r1]) * (2 * HID_);
        const float* Bj1 = g_AB + (size_t)(b * N_ + jjs[r1]) * (2 * HID_) + HID_;
        #pragma unroll
        for (int nt = 0; nt < 26; nt++) {
            int c = 8 * nt + e2c;
            acc[nt][0] = (c     < HID_) ? Ai0[c]     + Bj0[c]     : 0.f;
            acc[nt][1] = (c + 1 < HID_) ? Ai0[c + 1] + Bj0[c + 1] : 0.f;
            acc[nt][2] = (c     < HID_) ? Ai1[c]     + Bj1[c]     : 0.f;
            acc[nt][3] = (c + 1 < HID_) ? Ai1[c + 1] + Bj1[c + 1] : 0.f;
        }
    }

    // ---- Layer 1: 12 chunks of K=64, double-buffered ----
    fillB1(sb, 0, g_W1t, 0, tid);
    CP_COMMIT();
    fillA(sm, 0, embB, iis, jjs, 0, tid);
    CP_WAIT0();
    __syncthreads();
    for (int c = 0; c < 12; c++) {
        int nc = c + 1;
        if (nc < 12) {
            fillB1(sb, (nc & 1) * BB_SZ, g_W1t, nc * 64, tid);
            CP_COMMIT();
            fillA(sm, (nc & 1) * AB_SZ, embB, iis, jjs, nc * 64, tid);
        }
        mmaChunk1(sb, (c & 1) * AB_SZ, (c & 1) * BB_SZ, w, lane, acc);
        CP_WAIT0();
        __syncthreads();
    }

    // ---- relu h1 -> smem (bf16); reseed accumulators with b2 ----
    #pragma unroll
    for (int nt = 0; nt < 26; nt++) {
        int c = 8 * nt + e2c;
        *(uint32_t*)(sm + H1_OFF + r0 * (SH * 2) + c * 2) =
            packbf2(fmaxf(acc[nt][0], 0.f), fmaxf(acc[nt][1], 0.f));
        *(uint32_t*)(sm + H1_OFF + r1 * (SH * 2) + c * 2) =
            packbf2(fmaxf(acc[nt][2], 0.f), fmaxf(acc[nt][3], 0.f));
        float bb0 = b2s[c], bb1 = b2s[c + 1];
        acc[nt][0] = bb0; acc[nt][1] = bb1; acc[nt][2] = bb0; acc[nt][3] = bb1;
    }
    __syncthreads();

    // ---- Layer 2: 7 chunks of K=32 (last is 16 wide) ----
    fillB2(sb, 0, g_W2t, 0, tid);
    CP_COMMIT();
    CP_WAIT0();
    __syncthreads();
    for (int c = 0; c < 7; c++) {
        int nc = c + 1;
        if (nc < 7) {
            fillB2(sb, (nc & 1) * BB_SZ, g_W2t, nc * 32, tid);
            CP_COMMIT();
        }
        mmaChunk2(sb, (c & 1) * BB_SZ, c * 32, (c == 6) ? 1 : 2, w, lane, acc);
        CP_WAIT0();
        __syncthreads();
    }

    // ---- Layer 3: s = relu(h2) . W3 + b3 ----
    float s0 = 0.f, s1 = 0.f;
    #pragma unroll
    for (int nt = 0; nt < 26; nt++) {
        int c = 8 * nt + e2c;
        float w0 = w3s[c], w1v = w3s[c + 1];
        s0 = fmaf(fmaxf(acc[nt][0], 0.f), w0, s0);
        s0 = fmaf(fmaxf(acc[nt][1], 0.f), w1v, s0);
        s1 = fmaf(fmaxf(acc[nt][2], 0.f), w0, s1);
        s1 = fmaf(fmaxf(acc[nt][3], 0.f), w1v, s1);
    }
    s0 += __shfl_xor_sync(0xffffffffu, s0, 1);
    s0 += __shfl_xor_sync(0xffffffffu, s0, 2);
    s1 += __shfl_xor_sync(0xffffffffu, s1, 1);
    s1 += __shfl_xor_sync(0xffffffffu, s1, 2);
    if ((lane & 3) == 0) {
        float bb3 = b3[0];
        g_S[(size_t)(b * N_ + iis[r0]) * N_ + jjs[r0]] = s0 + bb3;
        g_S[(size_t)(b * N_ + iis[r1]) * N_ + jjs[r1]] = s1 + bb3;
    }
}

// ---------------- Stage 3: masked row softmax ----------------
__global__ void __launch_bounds__(128) softmax_kernel(float* __restrict__ out) {
    int blk = blockIdx.x;
    int i = blk & 255;
    const float* srow = g_S + (size_t)blk * N_;
    float* orow = out + (size_t)blk * N_;
    __shared__ float redm[4], redz[4];
    int tid = threadIdx.x;

    float m = (tid == 0) ? 0.f : -INFINITY;
    for (int j = tid; j < i; j += 128) m = fmaxf(m, srow[j]);
    #pragma unroll
    for (int o = 16; o; o >>= 1) m = fmaxf(m, __shfl_xor_sync(0xffffffffu, m, o));
    if ((tid & 31) == 0) redm[tid >> 5] = m;
    __syncthreads();
    m = fmaxf(fmaxf(redm[0], redm[1]), fmaxf(redm[2], redm[3]));

    float z = (tid == 0) ? expf(-m) : 0.f;
    for (int j = tid; j < i; j += 128) z += expf(srow[j] - m);
    #pragma unroll
    for (int o = 16; o; o >>= 1) z += __shfl_xor_sync(0xffffffffu, z, o);
    if ((tid & 31) == 0) redz[tid >> 5] = z;
    __syncthreads();
    z = redz[0] + redz[1] + redz[2] + redz[3];
    float invz = 1.f / z;

    for (int j = tid; j < N_; j += 128) {
        float o_;
        if (j < i)       o_ = expf(srow[j] - m) * invz;
        else if (j == i) o_ = expf(-m) * invz;
        else             o_ = -1000.0f;
        orow[j] = o_;
    }
}

// ---------------- launch ----------------
extern "C" void kernel_launch(void* const* d_in, const int* in_sizes, int n_in,
                              void* d_out, int out_size) {
    (void)in_sizes; (void)n_in; (void)out_size;
    const float* event_embed = (const float*)d_in[0];
    const int*   event_idx   = (const int*)d_in[1];
    const float* W1 = (const float*)d_in[2];
    const float* b1 = (const float*)d_in[3];
    const float* W2 = (const float*)d_in[4];
    const float* b2 = (const float*)d_in[5];
    const float* W3 = (const float*)d_in[6];
    const float* b3 = (const float*)d_in[7];
    float* out = (float*)d_out;

    cudaFuncSetAttribute(stage2_mma, cudaFuncAttributeMaxDynamicSharedMemorySize, SMEM_TOTAL);

    prep_weights<<<(NPAD * D_ + 255) / 256, 256>>>(W1, W2);
    stage1_kernel<<<B_ * N_ / 8, 256>>>(event_embed, event_idx, W1, b1);

    dim3 grid2(P_ / MT, B_);
    stage2_mma<<<grid2, THREADS, SMEM_TOTAL>>>(b2, W3, b3);

    softmax_kernel<<<B_ * N_, 128>>>(out);
}